// round 1
// baseline (speedup 1.0000x reference)
#include <cuda_runtime.h>
#include <math.h>

#define TK  2048   // tokens (B*S)
#define HD  2048   // hidden
#define FD  1408   // expert intermediate
#define NE  8      // experts
#define KT  2      // top-k
#define SFD 2816   // shared intermediate

// -------- scratch (device globals; no allocation allowed) --------
__device__ int   g_cnt[NE];
__device__ int   g_tok[NE][TK];
__device__ float g_wt [NE][TK];
__device__ float g_mid [(size_t)NE * TK * FD];   // routed silu(g)*u
__device__ float g_smid[(size_t)TK * SFD];       // shared silu(g)*u

// ---------------- routing ----------------
__global__ void zero_cnt_kernel() {
    if (threadIdx.x < NE) g_cnt[threadIdx.x] = 0;
}

__global__ void routing_kernel(const float* __restrict__ x,
                               const float* __restrict__ gw) {
    const int warp = threadIdx.x >> 5;
    const int lane = threadIdx.x & 31;
    const int t = blockIdx.x * (blockDim.x >> 5) + warp;
    if (t >= TK) return;
    const float* xr = x + (size_t)t * HD;
    float logit[NE];
    #pragma unroll
    for (int e = 0; e < NE; e++) {
        const float* w = gw + (size_t)e * HD;
        float s = 0.f;
        for (int i = lane; i < HD; i += 32) s += xr[i] * w[i];
        #pragma unroll
        for (int o = 16; o; o >>= 1) s += __shfl_xor_sync(0xffffffffu, s, o);
        logit[e] = s;  // all lanes hold full sum
    }
    if (lane == 0) {
        float mx = logit[0];
        #pragma unroll
        for (int e = 1; e < NE; e++) mx = fmaxf(mx, logit[e]);
        float p[NE]; float den = 0.f;
        #pragma unroll
        for (int e = 0; e < NE; e++) { p[e] = expf(logit[e] - mx); den += p[e]; }
        #pragma unroll
        for (int e = 0; e < NE; e++) p[e] /= den;
        int i1 = 0;
        #pragma unroll
        for (int e = 1; e < NE; e++) if (p[e] > p[i1]) i1 = e;
        int i2 = (i1 == 0) ? 1 : 0;
        #pragma unroll
        for (int e = 0; e < NE; e++) if (e != i1 && p[e] > p[i2]) i2 = e;
        int s1 = atomicAdd(&g_cnt[i1], 1);
        g_tok[i1][s1] = t; g_wt[i1][s1] = p[i1];
        int s2 = atomicAdd(&g_cnt[i2], 1);
        g_tok[i2][s2] = t; g_wt[i2][s2] = p[i2];
    }
}

// ---------------- tiled SGEMM kernels ----------------
#define BM 64
#define BN 64
#define BK 16

// routed gate+up fused, SiLU epilogue -> g_mid
__global__ __launch_bounds__(256) void routed_gateup(
    const float* __restrict__ X, const float* __restrict__ Gp,
    const float* __restrict__ Up)
{
    const int e   = blockIdx.z;
    const int cnt = g_cnt[e];
    const int m0  = blockIdx.y * BM;
    if (m0 >= cnt) return;
    const int n0  = blockIdx.x * BN;
    const float* G = Gp + (size_t)e * HD * FD;
    const float* U = Up + (size_t)e * HD * FD;
    __shared__ float As[BK][BM];
    __shared__ float Bg[BK][BN];
    __shared__ float Bu[BK][BN];
    const int tid = threadIdx.x;
    const int ar = tid >> 2, ac = (tid & 3) * 4;
    const int br = tid >> 4, bc = (tid & 15) * 4;
    const int tx = tid & 15, ty = tid >> 4;
    const float* xrow = nullptr;
    if (m0 + ar < cnt) xrow = X + (size_t)g_tok[e][m0 + ar] * HD;
    float ag[4][4], au[4][4];
    #pragma unroll
    for (int i = 0; i < 4; i++)
        #pragma unroll
        for (int j = 0; j < 4; j++) { ag[i][j] = 0.f; au[i][j] = 0.f; }

    for (int k0 = 0; k0 < HD; k0 += BK) {
        float4 av = xrow ? *(const float4*)(xrow + k0 + ac)
                         : make_float4(0.f, 0.f, 0.f, 0.f);
        As[ac+0][ar] = av.x; As[ac+1][ar] = av.y;
        As[ac+2][ar] = av.z; As[ac+3][ar] = av.w;
        *(float4*)&Bg[br][bc] = *(const float4*)(G + (size_t)(k0 + br) * FD + n0 + bc);
        *(float4*)&Bu[br][bc] = *(const float4*)(U + (size_t)(k0 + br) * FD + n0 + bc);
        __syncthreads();
        #pragma unroll
        for (int k = 0; k < BK; k++) {
            const float4 a  = *(const float4*)&As[k][ty * 4];
            const float4 vg = *(const float4*)&Bg[k][tx * 4];
            const float4 vu = *(const float4*)&Bu[k][tx * 4];
            const float aa[4] = {a.x, a.y, a.z, a.w};
            const float gg[4] = {vg.x, vg.y, vg.z, vg.w};
            const float uu[4] = {vu.x, vu.y, vu.z, vu.w};
            #pragma unroll
            for (int i = 0; i < 4; i++)
                #pragma unroll
                for (int j = 0; j < 4; j++) {
                    ag[i][j] += aa[i] * gg[j];
                    au[i][j] += aa[i] * uu[j];
                }
        }
        __syncthreads();
    }
    #pragma unroll
    for (int i = 0; i < 4; i++) {
        const int m = m0 + ty * 4 + i;
        if (m < cnt) {
            float* o = g_mid + ((size_t)e * TK + m) * FD + n0 + tx * 4;
            #pragma unroll
            for (int j = 0; j < 4; j++) {
                const float g = ag[i][j];
                o[j] = (g / (1.f + expf(-g))) * au[i][j];
            }
        }
    }
}

// routed down: g_mid @ down_proj[e], weighted atomic scatter into Out
__global__ __launch_bounds__(256) void routed_down(
    const float* __restrict__ Dp, float* __restrict__ Out)
{
    const int e   = blockIdx.z;
    const int cnt = g_cnt[e];
    const int m0  = blockIdx.y * BM;
    if (m0 >= cnt) return;
    const int n0  = blockIdx.x * BN;
    const float* D = Dp + (size_t)e * FD * HD;
    __shared__ float As[BK][BM];
    __shared__ float Bs[BK][BN];
    const int tid = threadIdx.x;
    const int ar = tid >> 2, ac = (tid & 3) * 4;
    const int br = tid >> 4, bc = (tid & 15) * 4;
    const int tx = tid & 15, ty = tid >> 4;
    const float* arow = (m0 + ar < cnt)
        ? g_mid + ((size_t)e * TK + m0 + ar) * FD : nullptr;
    float acc[4][4];
    #pragma unroll
    for (int i = 0; i < 4; i++)
        #pragma unroll
        for (int j = 0; j < 4; j++) acc[i][j] = 0.f;

    for (int k0 = 0; k0 < FD; k0 += BK) {
        float4 av = arow ? *(const float4*)(arow + k0 + ac)
                         : make_float4(0.f, 0.f, 0.f, 0.f);
        As[ac+0][ar] = av.x; As[ac+1][ar] = av.y;
        As[ac+2][ar] = av.z; As[ac+3][ar] = av.w;
        *(float4*)&Bs[br][bc] = *(const float4*)(D + (size_t)(k0 + br) * HD + n0 + bc);
        __syncthreads();
        #pragma unroll
        for (int k = 0; k < BK; k++) {
            const float4 a = *(const float4*)&As[k][ty * 4];
            const float4 b = *(const float4*)&Bs[k][tx * 4];
            const float aa[4] = {a.x, a.y, a.z, a.w};
            const float bb[4] = {b.x, b.y, b.z, b.w};
            #pragma unroll
            for (int i = 0; i < 4; i++)
                #pragma unroll
                for (int j = 0; j < 4; j++) acc[i][j] += aa[i] * bb[j];
        }
        __syncthreads();
    }
    #pragma unroll
    for (int i = 0; i < 4; i++) {
        const int m = m0 + ty * 4 + i;
        if (m < cnt) {
            const int   t = g_tok[e][m];
            const float w = g_wt[e][m];
            float* o = Out + (size_t)t * HD + n0 + tx * 4;
            #pragma unroll
            for (int j = 0; j < 4; j++) atomicAdd(&o[j], w * acc[i][j]);
        }
    }
}

// shared gate+up fused -> g_smid
__global__ __launch_bounds__(256) void shared_gateup(
    const float* __restrict__ X, const float* __restrict__ Gp,
    const float* __restrict__ Up)
{
    const int m0 = blockIdx.y * BM;
    const int n0 = blockIdx.x * BN;
    __shared__ float As[BK][BM];
    __shared__ float Bg[BK][BN];
    __shared__ float Bu[BK][BN];
    const int tid = threadIdx.x;
    const int ar = tid >> 2, ac = (tid & 3) * 4;
    const int br = tid >> 4, bc = (tid & 15) * 4;
    const int tx = tid & 15, ty = tid >> 4;
    const float* xrow = X + (size_t)(m0 + ar) * HD;
    float ag[4][4], au[4][4];
    #pragma unroll
    for (int i = 0; i < 4; i++)
        #pragma unroll
        for (int j = 0; j < 4; j++) { ag[i][j] = 0.f; au[i][j] = 0.f; }

    for (int k0 = 0; k0 < HD; k0 += BK) {
        float4 av = *(const float4*)(xrow + k0 + ac);
        As[ac+0][ar] = av.x; As[ac+1][ar] = av.y;
        As[ac+2][ar] = av.z; As[ac+3][ar] = av.w;
        *(float4*)&Bg[br][bc] = *(const float4*)(Gp + (size_t)(k0 + br) * SFD + n0 + bc);
        *(float4*)&Bu[br][bc] = *(const float4*)(Up + (size_t)(k0 + br) * SFD + n0 + bc);
        __syncthreads();
        #pragma unroll
        for (int k = 0; k < BK; k++) {
            const float4 a  = *(const float4*)&As[k][ty * 4];
            const float4 vg = *(const float4*)&Bg[k][tx * 4];
            const float4 vu = *(const float4*)&Bu[k][tx * 4];
            const float aa[4] = {a.x, a.y, a.z, a.w};
            const float gg[4] = {vg.x, vg.y, vg.z, vg.w};
            const float uu[4] = {vu.x, vu.y, vu.z, vu.w};
            #pragma unroll
            for (int i = 0; i < 4; i++)
                #pragma unroll
                for (int j = 0; j < 4; j++) {
                    ag[i][j] += aa[i] * gg[j];
                    au[i][j] += aa[i] * uu[j];
                }
        }
        __syncthreads();
    }
    #pragma unroll
    for (int i = 0; i < 4; i++) {
        const int m = m0 + ty * 4 + i;
        float* o = g_smid + (size_t)m * SFD + n0 + tx * 4;
        #pragma unroll
        for (int j = 0; j < 4; j++) {
            const float g = ag[i][j];
            o[j] = (g / (1.f + expf(-g))) * au[i][j];
        }
    }
}

// shared down: g_smid @ shared_down -> plain store (base of output)
__global__ __launch_bounds__(256) void shared_down(
    const float* __restrict__ Dp, float* __restrict__ Out)
{
    const int m0 = blockIdx.y * BM;
    const int n0 = blockIdx.x * BN;
    __shared__ float As[BK][BM];
    __shared__ float Bs[BK][BN];
    const int tid = threadIdx.x;
    const int ar = tid >> 2, ac = (tid & 3) * 4;
    const int br = tid >> 4, bc = (tid & 15) * 4;
    const int tx = tid & 15, ty = tid >> 4;
    const float* arow = g_smid + (size_t)(m0 + ar) * SFD;
    float acc[4][4];
    #pragma unroll
    for (int i = 0; i < 4; i++)
        #pragma unroll
        for (int j = 0; j < 4; j++) acc[i][j] = 0.f;

    for (int k0 = 0; k0 < SFD; k0 += BK) {
        float4 av = *(const float4*)(arow + k0 + ac);
        As[ac+0][ar] = av.x; As[ac+1][ar] = av.y;
        As[ac+2][ar] = av.z; As[ac+3][ar] = av.w;
        *(float4*)&Bs[br][bc] = *(const float4*)(Dp + (size_t)(k0 + br) * HD + n0 + bc);
        __syncthreads();
        #pragma unroll
        for (int k = 0; k < BK; k++) {
            const float4 a = *(const float4*)&As[k][ty * 4];
            const float4 b = *(const float4*)&Bs[k][tx * 4];
            const float aa[4] = {a.x, a.y, a.z, a.w};
            const float bb[4] = {b.x, b.y, b.z, b.w};
            #pragma unroll
            for (int i = 0; i < 4; i++)
                #pragma unroll
                for (int j = 0; j < 4; j++) acc[i][j] += aa[i] * bb[j];
        }
        __syncthreads();
    }
    #pragma unroll
    for (int i = 0; i < 4; i++) {
        const int m = m0 + ty * 4 + i;
        float* o = Out + (size_t)m * HD + n0 + tx * 4;
        #pragma unroll
        for (int j = 0; j < 4; j++) o[j] = acc[i][j];
    }
}

// ---------------- launch ----------------
extern "C" void kernel_launch(void* const* d_in, const int* in_sizes, int n_in,
                              void* d_out, int out_size) {
    const float* x  = (const float*)d_in[0];   // [T, H]
    const float* gw = (const float*)d_in[1];   // [E, H]
    const float* gp = (const float*)d_in[2];   // [E, H, F]
    const float* up = (const float*)d_in[3];   // [E, H, F]
    const float* dp = (const float*)d_in[4];   // [E, F, H]
    const float* sg = (const float*)d_in[5];   // [H, SF]
    const float* su = (const float*)d_in[6];   // [H, SF]
    const float* sd = (const float*)d_in[7];   // [SF, H]
    float* out = (float*)d_out;                // [T, H]

    zero_cnt_kernel<<<1, 32>>>();
    routing_kernel<<<TK / 8, 256>>>(x, gw);

    routed_gateup<<<dim3(FD / BN, TK / BM, NE), 256>>>(x, gp, up);
    shared_gateup<<<dim3(SFD / BN, TK / BM), 256>>>(x, sg, su);

    // shared_down writes the full output (plain stores) ...
    shared_down<<<dim3(HD / BN, TK / BM), 256>>>(sd, out);
    // ... then routed contributions scatter-add on top (stream-ordered after).
    routed_down<<<dim3(HD / BN, TK / BM, NE), 256>>>(dp, out);
}

// round 7
// speedup vs baseline: 1.9560x; 1.9560x over previous
#include <cuda_runtime.h>
#include <cuda_bf16.h>
#include <cstdint>
#include <math.h>

#define TKN 2048
#define HD  2048
#define FDI 1408
#define NE  8
#define SFD 2816

typedef __nv_bfloat16 bf16;

// ---------------- scratch ----------------
__device__ int   g_cnt[NE];
__device__ int   g_tok[NE][TKN];
__device__ float g_wt [NE][TKN];

__device__ bf16 g_xhi[(size_t)TKN * HD],  g_xlo[(size_t)TKN * HD];
__device__ bf16 g_gphi[(size_t)NE * FDI * HD], g_gplo[(size_t)NE * FDI * HD]; // [E][F][H]
__device__ bf16 g_uphi[(size_t)NE * FDI * HD], g_uplo[(size_t)NE * FDI * HD];
__device__ bf16 g_dphi[(size_t)NE * HD * FDI], g_dplo[(size_t)NE * HD * FDI]; // [E][H][F]
__device__ bf16 g_sghi[(size_t)SFD * HD], g_sglo[(size_t)SFD * HD];
__device__ bf16 g_suhi[(size_t)SFD * HD], g_sulo[(size_t)SFD * HD];
__device__ bf16 g_sdhi[(size_t)HD * SFD], g_sdlo[(size_t)HD * SFD];

__device__ float g_gt [(size_t)NE * TKN * FDI];   // routed gate fp32
__device__ float g_ut [(size_t)NE * TKN * FDI];   // routed up fp32
__device__ float g_sgt[(size_t)TKN * SFD];
__device__ float g_sut[(size_t)TKN * SFD];
__device__ bf16 g_midhi[(size_t)NE * TKN * FDI], g_midlo[(size_t)NE * TKN * FDI];
__device__ bf16 g_smidhi[(size_t)TKN * SFD], g_smidlo[(size_t)TKN * SFD];

// ---------------- helpers ----------------
__device__ __forceinline__ uint32_t smem_u32(const void* p) {
    uint32_t a;
    asm("{ .reg .u64 t; cvta.to.shared.u64 t, %1; cvt.u32.u64 %0, t; }"
        : "=r"(a) : "l"(p));
    return a;
}

#define CP_ASYNC16(saddr, gptr, sz) \
    asm volatile("cp.async.cg.shared.global [%0], [%1], 16, %2;" \
                 :: "r"(saddr), "l"(gptr), "r"(sz))
#define CP_COMMIT()  asm volatile("cp.async.commit_group;")
#define CP_WAIT(N)   asm volatile("cp.async.wait_group %0;" :: "n"(N))

#define LDSM4(R0, R1, R2, R3, ADDR) \
    asm volatile("ldmatrix.sync.aligned.m8n8.x4.shared.b16 {%0,%1,%2,%3}, [%4];" \
                 : "=r"(R0), "=r"(R1), "=r"(R2), "=r"(R3) : "r"(ADDR))

#define MMA16816(D, A0, A1, A2, A3, B0, B1) \
    asm volatile("mma.sync.aligned.m16n8k16.row.col.f32.bf16.bf16.f32 " \
                 "{%0,%1,%2,%3}, {%4,%5,%6,%7}, {%8,%9}, {%0,%1,%2,%3};" \
                 : "+f"(D[0]), "+f"(D[1]), "+f"(D[2]), "+f"(D[3]) \
                 : "r"(A0), "r"(A1), "r"(A2), "r"(A3), "r"(B0), "r"(B1))

// ---------------- routing ----------------
__global__ void zero_cnt_kernel() {
    if (threadIdx.x < NE) g_cnt[threadIdx.x] = 0;
}

__global__ void routing_kernel(const float* __restrict__ x,
                               const float* __restrict__ gw) {
    const int warp = threadIdx.x >> 5;
    const int lane = threadIdx.x & 31;
    const int t = blockIdx.x * (blockDim.x >> 5) + warp;
    if (t >= TKN) return;
    const float* xr = x + (size_t)t * HD;
    float logit[NE];
    #pragma unroll
    for (int e = 0; e < NE; e++) {
        const float* w = gw + (size_t)e * HD;
        float s = 0.f;
        for (int i = lane; i < HD; i += 32) s += xr[i] * w[i];
        #pragma unroll
        for (int o = 16; o; o >>= 1) s += __shfl_xor_sync(0xffffffffu, s, o);
        logit[e] = s;
    }
    if (lane == 0) {
        float mx = logit[0];
        #pragma unroll
        for (int e = 1; e < NE; e++) mx = fmaxf(mx, logit[e]);
        float p[NE]; float den = 0.f;
        #pragma unroll
        for (int e = 0; e < NE; e++) { p[e] = expf(logit[e] - mx); den += p[e]; }
        #pragma unroll
        for (int e = 0; e < NE; e++) p[e] /= den;
        int i1 = 0;
        #pragma unroll
        for (int e = 1; e < NE; e++) if (p[e] > p[i1]) i1 = e;
        int i2 = (i1 == 0) ? 1 : 0;
        #pragma unroll
        for (int e = 0; e < NE; e++) if (e != i1 && p[e] > p[i2]) i2 = e;
        int s1 = atomicAdd(&g_cnt[i1], 1);
        g_tok[i1][s1] = t; g_wt[i1][s1] = p[i1];
        int s2 = atomicAdd(&g_cnt[i2], 1);
        g_tok[i2][s2] = t; g_wt[i2][s2] = p[i2];
    }
}

// ---------------- conversions ----------------
__global__ void split_kernel(const float* __restrict__ src,
                             bf16* __restrict__ hi, bf16* __restrict__ lo,
                             int n4) {
    int i = blockIdx.x * blockDim.x + threadIdx.x;
    if (i >= n4) return;
    float4 v = ((const float4*)src)[i];
    float vv[4] = {v.x, v.y, v.z, v.w};
    #pragma unroll
    for (int j = 0; j < 4; j++) {
        bf16 h = __float2bfloat16(vv[j]);
        hi[i * 4 + j] = h;
        lo[i * 4 + j] = __float2bfloat16(vv[j] - __bfloat162float(h));
    }
}

// src [z][K][N] -> dst [z][N][K] split hi/lo
__global__ void transpose_split_kernel(const float* __restrict__ src,
                                       bf16* __restrict__ hi, bf16* __restrict__ lo,
                                       int K, int N) {
    __shared__ float t[32][33];
    const size_t b = (size_t)blockIdx.z * K * N;
    const int x0 = blockIdx.x * 32, y0 = blockIdx.y * 32;
    const int tx = threadIdx.x, ty = threadIdx.y;
    #pragma unroll
    for (int j = 0; j < 32; j += 8)
        t[ty + j][tx] = src[b + (size_t)(y0 + ty + j) * N + x0 + tx];
    __syncthreads();
    #pragma unroll
    for (int j = 0; j < 32; j += 8) {
        float v = t[tx][ty + j];
        bf16 h = __float2bfloat16(v);
        size_t o = b + (size_t)(x0 + ty + j) * K + y0 + tx;
        hi[o] = h;
        lo[o] = __float2bfloat16(v - __bfloat162float(h));
    }
}

// ---------------- HMMA GEMM ----------------
// C[m,n] = sum_k A[m,k]*B[n,k]  with hi/lo 3-pass split.
// CTA tile 128x128, K-chunk 32, 8 warps (2M x 4N), warp tile 64x32.
// EPI: 0 = store fp32 scratch (ld = Ntot), 1 = routed weighted atomic to Out,
//      2 = plain store to Out.
#define BM 128
#define BN 128
#define BK 32
#define STRIDE 40                        // bf16 elems per smem row (80B, conflict-free)
#define STAGE_ELEMS (4 * 128 * STRIDE)   // Ah,Al,Bh,Bl per stage
#define GEMM_SMEM (2 * STAGE_ELEMS * 2)  // bytes (81920)

template<bool ROUTED, bool GATHER, int EPI>
__global__ __launch_bounds__(256, 1) void gemm_hmma(
    const bf16* __restrict__ Ahi, const bf16* __restrict__ Alo,
    const bf16* __restrict__ Bhi, const bf16* __restrict__ Blo,
    float* __restrict__ C, int Ntot, int Ktot)
{
    extern __shared__ bf16 smem[];
    const int e   = ROUTED ? blockIdx.z : 0;
    const int cnt = ROUTED ? g_cnt[e] : TKN;
    const int m0  = blockIdx.y * BM;
    if (m0 >= cnt) return;
    const int n0  = blockIdx.x * BN;
    const int tid = threadIdx.x;
    const int wid = tid >> 5, lane = tid & 31;
    const int wm = wid >> 2, wn = wid & 3;

    const uint32_t sbase = smem_u32(smem);
    // per-thread load slots: row = tid>>2 (+64), col chunk = (tid&3)*8
    const int lr = tid >> 2;
    const int lc = (tid & 3) * 8;

    // A row sources (2 rows per thread)
    const bf16* aptr_hi[2]; const bf16* aptr_lo[2]; uint32_t asz[2];
    #pragma unroll
    for (int it = 0; it < 2; it++) {
        const int m = m0 + lr + it * 64;
        long row;
        if (m < cnt) {
            if (GATHER)      row = g_tok[e][m];
            else if (ROUTED) row = (long)e * TKN + m;
            else             row = m;
            asz[it] = 16;
        } else { row = 0; asz[it] = 0; }
        aptr_hi[it] = Ahi + (size_t)row * Ktot + lc;
        aptr_lo[it] = Alo + (size_t)row * Ktot + lc;
    }
    const size_t wb = ROUTED ? (size_t)e * Ntot * Ktot : 0;
    const bf16* bptr_hi[2]; const bf16* bptr_lo[2];
    #pragma unroll
    for (int it = 0; it < 2; it++) {
        const int n = n0 + lr + it * 64;
        bptr_hi[it] = Bhi + wb + (size_t)n * Ktot + lc;
        bptr_lo[it] = Blo + wb + (size_t)n * Ktot + lc;
    }
    // smem dst addresses (bytes)
    uint32_t sA[2], sB[2];
    #pragma unroll
    for (int it = 0; it < 2; it++) {
        const uint32_t off = ((lr + it * 64) * STRIDE + lc) * 2;
        sA[it] = sbase + off;
        sB[it] = sbase + off;
    }
    const uint32_t OFF_AL = 128 * STRIDE * 2;
    const uint32_t OFF_BH = 2 * OFF_AL;
    const uint32_t OFF_BL = 3 * OFF_AL;
    const uint32_t STG = STAGE_ELEMS * 2;

    float acc[4][4][4];
    #pragma unroll
    for (int a = 0; a < 4; a++)
        #pragma unroll
        for (int b = 0; b < 4; b++)
            #pragma unroll
            for (int c = 0; c < 4; c++) acc[a][b][c] = 0.f;

    const int nch = Ktot / BK;

    // prefetch chunk 0 -> stage 0
    #pragma unroll
    for (int it = 0; it < 2; it++) {
        CP_ASYNC16(sA[it],          aptr_hi[it], asz[it]);
        CP_ASYNC16(sA[it] + OFF_AL, aptr_lo[it], asz[it]);
        CP_ASYNC16(sB[it] + OFF_BH, bptr_hi[it], 16u);
        CP_ASYNC16(sB[it] + OFF_BL, bptr_lo[it], 16u);
    }
    CP_COMMIT();

    for (int ch = 0; ch < nch; ch++) {
        if (ch + 1 < nch) {
            const uint32_t st = ((ch + 1) & 1) * STG;
            const int ko = (ch + 1) * BK;
            #pragma unroll
            for (int it = 0; it < 2; it++) {
                CP_ASYNC16(sA[it] + st,          aptr_hi[it] + ko, asz[it]);
                CP_ASYNC16(sA[it] + st + OFF_AL, aptr_lo[it] + ko, asz[it]);
                CP_ASYNC16(sB[it] + st + OFF_BH, bptr_hi[it] + ko, 16u);
                CP_ASYNC16(sB[it] + st + OFF_BL, bptr_lo[it] + ko, 16u);
            }
            CP_COMMIT();
            CP_WAIT(1);
        } else {
            CP_WAIT(0);
        }
        __syncthreads();

        const uint32_t st = (ch & 1) * STG;
        #pragma unroll
        for (int ks = 0; ks < 2; ks++) {
            const int col = ks * 16 + ((lane >> 4) << 3);  // bf16 col for ldmatrix
            uint32_t ah[4][4], al[4][4];
            #pragma unroll
            for (int mf = 0; mf < 4; mf++) {
                const int row = wm * 64 + mf * 16 + (lane & 15);
                const uint32_t a = sbase + st + (row * STRIDE + col) * 2;
                LDSM4(ah[mf][0], ah[mf][1], ah[mf][2], ah[mf][3], a);
                LDSM4(al[mf][0], al[mf][1], al[mf][2], al[mf][3], a + OFF_AL);
            }
            uint32_t bh[4][2], bl[4][2];
            #pragma unroll
            for (int nf2 = 0; nf2 < 2; nf2++) {
                const int row = wn * 32 + nf2 * 16 + (lane & 15);
                const uint32_t a = sbase + st + (row * STRIDE + col) * 2;
                LDSM4(bh[nf2*2][0], bh[nf2*2+1][0], bh[nf2*2][1], bh[nf2*2+1][1], a + OFF_BH);
                LDSM4(bl[nf2*2][0], bl[nf2*2+1][0], bl[nf2*2][1], bl[nf2*2+1][1], a + OFF_BL);
            }
            #pragma unroll
            for (int mf = 0; mf < 4; mf++)
                #pragma unroll
                for (int nf = 0; nf < 4; nf++) {
                    MMA16816(acc[mf][nf], ah[mf][0], ah[mf][1], ah[mf][2], ah[mf][3],
                             bh[nf][0], bh[nf][1]);
                    MMA16816(acc[mf][nf], ah[mf][0], ah[mf][1], ah[mf][2], ah[mf][3],
                             bl[nf][0], bl[nf][1]);
                    MMA16816(acc[mf][nf], al[mf][0], al[mf][1], al[mf][2], al[mf][3],
                             bh[nf][0], bh[nf][1]);
                }
        }
        __syncthreads();
    }

    // epilogue
    const int quad = lane >> 2, tq = lane & 3;
    #pragma unroll
    for (int mf = 0; mf < 4; mf++) {
        #pragma unroll
        for (int half = 0; half < 2; half++) {
            const int m = wm * 64 + mf * 16 + half * 8 + quad;   // local row
            const int gm = m0 + m;
            if (gm >= cnt) continue;
            if (EPI == 0) {
                float* o = C + ((size_t)(ROUTED ? (size_t)e * TKN : 0) + gm) * Ntot
                             + n0 + wn * 32 + tq * 2;
                #pragma unroll
                for (int nf = 0; nf < 4; nf++) {
                    o[nf * 8 + 0] = acc[mf][nf][half * 2 + 0];
                    o[nf * 8 + 1] = acc[mf][nf][half * 2 + 1];
                }
            } else if (EPI == 1) {
                const int   t = g_tok[e][gm];
                const float w = g_wt[e][gm];
                float* o = C + (size_t)t * HD + n0 + wn * 32 + tq * 2;
                #pragma unroll
                for (int nf = 0; nf < 4; nf++) {
                    atomicAdd(&o[nf * 8 + 0], w * acc[mf][nf][half * 2 + 0]);
                    atomicAdd(&o[nf * 8 + 1], w * acc[mf][nf][half * 2 + 1]);
                }
            } else {
                float* o = C + (size_t)gm * HD + n0 + wn * 32 + tq * 2;
                #pragma unroll
                for (int nf = 0; nf < 4; nf++) {
                    o[nf * 8 + 0] = acc[mf][nf][half * 2 + 0];
                    o[nf * 8 + 1] = acc[mf][nf][half * 2 + 1];
                }
            }
        }
    }
}

// ---------------- silu * up -> bf16 split ----------------
template<bool ROUTED>
__global__ void silu_split_kernel(const float* __restrict__ G,
                                  const float* __restrict__ U,
                                  bf16* __restrict__ Mhi, bf16* __restrict__ Mlo,
                                  int Ntot, int rows) {
    const int n4 = Ntot / 4;
    int i = blockIdx.x * blockDim.x + threadIdx.x;
    if (i >= rows * n4) return;
    const int row = i / n4;
    if (ROUTED) {
        const int m = row % TKN;
        if (m >= g_cnt[row / TKN]) return;
    }
    float4 g4 = ((const float4*)G)[i];
    float4 u4 = ((const float4*)U)[i];
    float gg[4] = {g4.x, g4.y, g4.z, g4.w};
    float uu[4] = {u4.x, u4.y, u4.z, u4.w};
    #pragma unroll
    for (int j = 0; j < 4; j++) {
        float h = gg[j] / (1.f + __expf(-gg[j])) * uu[j];
        bf16 hh = __float2bfloat16(h);
        Mhi[i * 4 + j] = hh;
        Mlo[i * 4 + j] = __float2bfloat16(h - __bfloat162float(hh));
    }
}

// ---------------- launch ----------------
#define GETSYM(var, sym) void* var = nullptr; cudaGetSymbolAddress(&var, sym)

extern "C" void kernel_launch(void* const* d_in, const int* in_sizes, int n_in,
                              void* d_out, int out_size) {
    const float* x  = (const float*)d_in[0];
    const float* gw = (const float*)d_in[1];
    const float* gp = (const float*)d_in[2];
    const float* up = (const float*)d_in[3];
    const float* dp = (const float*)d_in[4];
    const float* sg = (const float*)d_in[5];
    const float* su = (const float*)d_in[6];
    const float* sd = (const float*)d_in[7];
    float* out = (float*)d_out;

    GETSYM(p_xhi, g_xhi);   GETSYM(p_xlo, g_xlo);
    GETSYM(p_gphi, g_gphi); GETSYM(p_gplo, g_gplo);
    GETSYM(p_uphi, g_uphi); GETSYM(p_uplo, g_uplo);
    GETSYM(p_dphi, g_dphi); GETSYM(p_dplo, g_dplo);
    GETSYM(p_sghi, g_sghi); GETSYM(p_sglo, g_sglo);
    GETSYM(p_suhi, g_suhi); GETSYM(p_sulo, g_sulo);
    GETSYM(p_sdhi, g_sdhi); GETSYM(p_sdlo, g_sdlo);
    GETSYM(p_gt, g_gt);     GETSYM(p_ut, g_ut);
    GETSYM(p_sgt, g_sgt);   GETSYM(p_sut, g_sut);
    GETSYM(p_midhi, g_midhi); GETSYM(p_midlo, g_midlo);
    GETSYM(p_smidhi, g_smidhi); GETSYM(p_smidlo, g_smidlo);

    cudaFuncSetAttribute(gemm_hmma<true, true, 0>,  cudaFuncAttributeMaxDynamicSharedMemorySize, GEMM_SMEM);
    cudaFuncSetAttribute(gemm_hmma<false, false, 0>, cudaFuncAttributeMaxDynamicSharedMemorySize, GEMM_SMEM);
    cudaFuncSetAttribute(gemm_hmma<true, false, 1>, cudaFuncAttributeMaxDynamicSharedMemorySize, GEMM_SMEM);
    cudaFuncSetAttribute(gemm_hmma<false, false, 2>, cudaFuncAttributeMaxDynamicSharedMemorySize, GEMM_SMEM);

    zero_cnt_kernel<<<1, 32>>>();
    routing_kernel<<<TKN / 8, 256>>>(x, gw);

    split_kernel<<<(TKN * HD / 4 + 255) / 256, 256>>>(x, (bf16*)p_xhi, (bf16*)p_xlo, TKN * HD / 4);
    transpose_split_kernel<<<dim3(FDI / 32, HD / 32, NE), dim3(32, 8)>>>(gp, (bf16*)p_gphi, (bf16*)p_gplo, HD, FDI);
    transpose_split_kernel<<<dim3(FDI / 32, HD / 32, NE), dim3(32, 8)>>>(up, (bf16*)p_uphi, (bf16*)p_uplo, HD, FDI);
    transpose_split_kernel<<<dim3(HD / 32, FDI / 32, NE), dim3(32, 8)>>>(dp, (bf16*)p_dphi, (bf16*)p_dplo, FDI, HD);
    transpose_split_kernel<<<dim3(SFD / 32, HD / 32, 1), dim3(32, 8)>>>(sg, (bf16*)p_sghi, (bf16*)p_sglo, HD, SFD);
    transpose_split_kernel<<<dim3(SFD / 32, HD / 32, 1), dim3(32, 8)>>>(su, (bf16*)p_suhi, (bf16*)p_sulo, HD, SFD);
    transpose_split_kernel<<<dim3(HD / 32, SFD / 32, 1), dim3(32, 8)>>>(sd, (bf16*)p_sdhi, (bf16*)p_sdlo, SFD, HD);

    // routed gate & up: C fp32 scratch
    gemm_hmma<true, true, 0><<<dim3(FDI / BN, TKN / BM, NE), 256, GEMM_SMEM>>>(
        (const bf16*)p_xhi, (const bf16*)p_xlo,
        (const bf16*)p_gphi, (const bf16*)p_gplo, (float*)p_gt, FDI, HD);
    gemm_hmma<true, true, 0><<<dim3(FDI / BN, TKN / BM, NE), 256, GEMM_SMEM>>>(
        (const bf16*)p_xhi, (const bf16*)p_xlo,
        (const bf16*)p_uphi, (const bf16*)p_uplo, (float*)p_ut, FDI, HD);
    // shared gate & up
    gemm_hmma<false, false, 0><<<dim3(SFD / BN, TKN / BM), 256, GEMM_SMEM>>>(
        (const bf16*)p_xhi, (const bf16*)p_xlo,
        (const bf16*)p_sghi, (const bf16*)p_sglo, (float*)p_sgt, SFD, HD);
    gemm_hmma<false, false, 0><<<dim3(SFD / BN, TKN / BM), 256, GEMM_SMEM>>>(
        (const bf16*)p_xhi, (const bf16*)p_xlo,
        (const bf16*)p_suhi, (const bf16*)p_sulo, (float*)p_sut, SFD, HD);

    // silu * up -> bf16 split
    silu_split_kernel<true><<<((NE * TKN) * (FDI / 4) + 255) / 256, 256>>>(
        (const float*)p_gt, (const float*)p_ut,
        (bf16*)p_midhi, (bf16*)p_midlo, FDI, NE * TKN);
    silu_split_kernel<false><<<(TKN * (SFD / 4) + 255) / 256, 256>>>(
        (const float*)p_sgt, (const float*)p_sut,
        (bf16*)p_smidhi, (bf16*)p_smidlo, SFD, TKN);

    // shared down writes full output, then routed down scatters on top
    gemm_hmma<false, false, 2><<<dim3(HD / BN, TKN / BM), 256, GEMM_SMEM>>>(
        (const bf16*)p_smidhi, (const bf16*)p_smidlo,
        (const bf16*)p_sdhi, (const bf16*)p_sdlo, out, HD, SFD);
    gemm_hmma<true, false, 1><<<dim3(HD / BN, TKN / BM, NE), 256, GEMM_SMEM>>>(
        (const bf16*)p_midhi, (const bf16*)p_midlo,
        (const bf16*)p_dphi, (const bf16*)p_dplo, out, HD, FDI);
}

// round 13
// speedup vs baseline: 2.3729x; 1.2132x over previous
#include <cuda_runtime.h>
#include <cuda_bf16.h>
#include <cstdint>
#include <math.h>

#define TKN 2048
#define HD  2048
#define FDI 1408
#define NE  8
#define SFD 2816

typedef __nv_bfloat16 bf16;

// ---------------- scratch ----------------
__device__ int   g_cnt[NE];
__device__ int   g_tok[NE][TKN];
__device__ float g_wt [NE][TKN];

__device__ bf16 g_xhi[(size_t)TKN * HD],  g_xlo[(size_t)TKN * HD];
__device__ bf16 g_gphi[(size_t)NE * FDI * HD], g_gplo[(size_t)NE * FDI * HD]; // [E][F][H]
__device__ bf16 g_uphi[(size_t)NE * FDI * HD], g_uplo[(size_t)NE * FDI * HD];
__device__ bf16 g_dphi[(size_t)NE * HD * FDI], g_dplo[(size_t)NE * HD * FDI]; // [E][H][F]
__device__ bf16 g_sghi[(size_t)SFD * HD], g_sglo[(size_t)SFD * HD];
__device__ bf16 g_suhi[(size_t)SFD * HD], g_sulo[(size_t)SFD * HD];
__device__ bf16 g_sdhi[(size_t)HD * SFD], g_sdlo[(size_t)HD * SFD];

__device__ bf16 g_midhi[(size_t)NE * TKN * FDI], g_midlo[(size_t)NE * TKN * FDI];
__device__ bf16 g_smidhi[(size_t)TKN * SFD], g_smidlo[(size_t)TKN * SFD];

// ---------------- helpers ----------------
__device__ __forceinline__ uint32_t smem_u32(const void* p) {
    uint32_t a;
    asm("{ .reg .u64 t; cvta.to.shared.u64 t, %1; cvt.u32.u64 %0, t; }"
        : "=r"(a) : "l"(p));
    return a;
}

#define CP_ASYNC16(saddr, gptr, sz) \
    asm volatile("cp.async.cg.shared.global [%0], [%1], 16, %2;" \
                 :: "r"(saddr), "l"(gptr), "r"(sz))
#define CP_COMMIT()  asm volatile("cp.async.commit_group;")
#define CP_WAIT(N)   asm volatile("cp.async.wait_group %0;" :: "n"(N))

#define LDSM4(R0, R1, R2, R3, ADDR) \
    asm volatile("ldmatrix.sync.aligned.m8n8.x4.shared.b16 {%0,%1,%2,%3}, [%4];" \
                 : "=r"(R0), "=r"(R1), "=r"(R2), "=r"(R3) : "r"(ADDR))

#define MMA16816(D, A0, A1, A2, A3, B0, B1) \
    asm volatile("mma.sync.aligned.m16n8k16.row.col.f32.bf16.bf16.f32 " \
                 "{%0,%1,%2,%3}, {%4,%5,%6,%7}, {%8,%9}, {%0,%1,%2,%3};" \
                 : "+f"(D[0]), "+f"(D[1]), "+f"(D[2]), "+f"(D[3]) \
                 : "r"(A0), "r"(A1), "r"(A2), "r"(A3), "r"(B0), "r"(B1))

// ---------------- routing ----------------
__global__ void zero_cnt_kernel() {
    if (threadIdx.x < NE) g_cnt[threadIdx.x] = 0;
}

__global__ void routing_kernel(const float* __restrict__ x,
                               const float* __restrict__ gw) {
    const int warp = threadIdx.x >> 5;
    const int lane = threadIdx.x & 31;
    const int t = blockIdx.x * (blockDim.x >> 5) + warp;
    if (t >= TKN) return;
    const float* xr = x + (size_t)t * HD;
    float logit[NE];
    #pragma unroll
    for (int e = 0; e < NE; e++) {
        const float* w = gw + (size_t)e * HD;
        float s = 0.f;
        for (int i = lane; i < HD; i += 32) s += xr[i] * w[i];
        #pragma unroll
        for (int o = 16; o; o >>= 1) s += __shfl_xor_sync(0xffffffffu, s, o);
        logit[e] = s;
    }
    if (lane == 0) {
        float mx = logit[0];
        #pragma unroll
        for (int e = 1; e < NE; e++) mx = fmaxf(mx, logit[e]);
        float p[NE]; float den = 0.f;
        #pragma unroll
        for (int e = 0; e < NE; e++) { p[e] = expf(logit[e] - mx); den += p[e]; }
        #pragma unroll
        for (int e = 0; e < NE; e++) p[e] /= den;
        int i1 = 0;
        #pragma unroll
        for (int e = 1; e < NE; e++) if (p[e] > p[i1]) i1 = e;
        int i2 = (i1 == 0) ? 1 : 0;
        #pragma unroll
        for (int e = 0; e < NE; e++) if (e != i1 && p[e] > p[i2]) i2 = e;
        int s1 = atomicAdd(&g_cnt[i1], 1);
        g_tok[i1][s1] = t; g_wt[i1][s1] = p[i1];
        int s2 = atomicAdd(&g_cnt[i2], 1);
        g_tok[i2][s2] = t; g_wt[i2][s2] = p[i2];
    }
}

// ---------------- conversions ----------------
__global__ void split_kernel(const float* __restrict__ src,
                             bf16* __restrict__ hi, bf16* __restrict__ lo,
                             int n4) {
    int i = blockIdx.x * blockDim.x + threadIdx.x;
    if (i >= n4) return;
    float4 v = ((const float4*)src)[i];
    float vv[4] = {v.x, v.y, v.z, v.w};
    #pragma unroll
    for (int j = 0; j < 4; j++) {
        bf16 h = __float2bfloat16(vv[j]);
        hi[i * 4 + j] = h;
        lo[i * 4 + j] = __float2bfloat16(vv[j] - __bfloat162float(h));
    }
}

// all 6 weight transposes in ONE launch (keeps ncu -s 5 on a GEMM next round)
#define NB_GP 22528   // (FDI/32)*(HD/32)*NE
#define NB_SG 5632    // (SFD/32)*(HD/32)
__global__ void conv_all_kernel(const float* __restrict__ gp,
                                const float* __restrict__ up,
                                const float* __restrict__ dp,
                                const float* __restrict__ sg,
                                const float* __restrict__ su,
                                const float* __restrict__ sd) {
    __shared__ float t[32][33];
    int b = blockIdx.x;
    const float* src; bf16 *hi, *lo; int K, N;
    if (b < NB_GP)              { src = gp; hi = g_gphi; lo = g_gplo; K = HD;  N = FDI; }
    else if (b < 2 * NB_GP)     { b -= NB_GP;     src = up; hi = g_uphi; lo = g_uplo; K = HD;  N = FDI; }
    else if (b < 3 * NB_GP)     { b -= 2 * NB_GP; src = dp; hi = g_dphi; lo = g_dplo; K = FDI; N = HD;  }
    else if (b < 3 * NB_GP + NB_SG)     { b -= 3 * NB_GP;         src = sg; hi = g_sghi; lo = g_sglo; K = HD;  N = SFD; }
    else if (b < 3 * NB_GP + 2 * NB_SG) { b -= 3 * NB_GP + NB_SG; src = su; hi = g_suhi; lo = g_sulo; K = HD;  N = SFD; }
    else                        { b -= 3 * NB_GP + 2 * NB_SG;     src = sd; hi = g_sdhi; lo = g_sdlo; K = SFD; N = HD;  }
    const int tilesX = N >> 5, tilesY = K >> 5;
    const int perZ = tilesX * tilesY;
    const int z = b / perZ, r = b % perZ;
    const int x0 = (r % tilesX) * 32, y0 = (r / tilesX) * 32;
    const size_t base = (size_t)z * K * N;
    const int tx = threadIdx.x, ty = threadIdx.y;   // (32, 8)
    #pragma unroll
    for (int j = 0; j < 32; j += 8)
        t[ty + j][tx] = src[base + (size_t)(y0 + ty + j) * N + x0 + tx];
    __syncthreads();
    #pragma unroll
    for (int j = 0; j < 32; j += 8) {
        float v = t[tx][ty + j];
        bf16 h = __float2bfloat16(v);
        size_t o = base + (size_t)(x0 + ty + j) * K + y0 + tx;
        hi[o] = h;
        lo[o] = __float2bfloat16(v - __bfloat162float(h));
    }
}

// ---------------- fused gate+up GEMM + SiLU epilogue ----------------
// CTA 128(M) x 64(N), BK=32, 8 warps (4M x 2N), warp tile 32x32.
// Computes G = A.Bg, U = A.Bu (3-pass hi/lo each), writes silu(G)*U split
// to Mhi/Mlo directly.
#define BK 32
#define STRIDE 40                          // bf16 elems per smem row (80B)
#define F_A_BYTES (128 * STRIDE * 2)       // 10240
#define F_B_BYTES (64 * STRIDE * 2)        // 5120
#define F_STAGE (2 * F_A_BYTES + 4 * F_B_BYTES)  // 40960
#define FUSE_SMEM (2 * F_STAGE)            // 81920

template<bool ROUTED>
__global__ __launch_bounds__(256, 2) void gateup_fused(
    const bf16* __restrict__ Ahi, const bf16* __restrict__ Alo,
    const bf16* __restrict__ Ghi, const bf16* __restrict__ Glo,
    const bf16* __restrict__ Uhi, const bf16* __restrict__ Ulo,
    bf16* __restrict__ Mhi, bf16* __restrict__ Mlo,
    int Ntot, int Ktot)
{
    extern __shared__ bf16 smem[];
    const int e   = ROUTED ? blockIdx.z : 0;
    const int cnt = ROUTED ? g_cnt[e] : TKN;
    const int m0  = blockIdx.y * 128;
    if (m0 >= cnt) return;
    const int n0  = blockIdx.x * 64;
    const int tid = threadIdx.x;
    const int wid = tid >> 5, lane = tid & 31;
    const int wm = wid >> 1, wn = wid & 1;

    const uint32_t sbase = smem_u32(smem);
    const int lr = tid >> 2;               // 0..63
    const int lc = (tid & 3) * 8;          // bf16 col chunk

    // A: rows lr and lr+64 (gathered for ROUTED)
    const bf16* aptr_hi[2]; const bf16* aptr_lo[2]; uint32_t asz[2];
    #pragma unroll
    for (int it = 0; it < 2; it++) {
        const int m = m0 + lr + it * 64;
        long row = 0;
        if (m < cnt) { row = ROUTED ? g_tok[e][m] : m; asz[it] = 16; }
        else asz[it] = 0;
        aptr_hi[it] = Ahi + (size_t)row * Ktot + lc;
        aptr_lo[it] = Alo + (size_t)row * Ktot + lc;
    }
    const size_t wb = ROUTED ? (size_t)e * Ntot * Ktot : 0;
    const size_t boff = wb + (size_t)(n0 + lr) * Ktot + lc;
    const bf16* gph = Ghi + boff; const bf16* gpl = Glo + boff;
    const bf16* uph = Uhi + boff; const bf16* upl = Ulo + boff;

    uint32_t sA[2];
    #pragma unroll
    for (int it = 0; it < 2; it++)
        sA[it] = sbase + ((lr + it * 64) * STRIDE + lc) * 2;
    const uint32_t sB = sbase + (lr * STRIDE + lc) * 2;
    const uint32_t O_AL = F_A_BYTES;
    const uint32_t O_GH = 2 * F_A_BYTES;
    const uint32_t O_GL = O_GH + F_B_BYTES;
    const uint32_t O_UH = O_GL + F_B_BYTES;
    const uint32_t O_UL = O_UH + F_B_BYTES;

    float accg[2][4][4], accu[2][4][4];
    #pragma unroll
    for (int a = 0; a < 2; a++)
        #pragma unroll
        for (int b = 0; b < 4; b++)
            #pragma unroll
            for (int c = 0; c < 4; c++) { accg[a][b][c] = 0.f; accu[a][b][c] = 0.f; }

    const int nch = Ktot / BK;

    #pragma unroll
    for (int it = 0; it < 2; it++) {
        CP_ASYNC16(sA[it],        aptr_hi[it], asz[it]);
        CP_ASYNC16(sA[it] + O_AL, aptr_lo[it], asz[it]);
    }
    CP_ASYNC16(sB + O_GH, gph, 16u);
    CP_ASYNC16(sB + O_GL, gpl, 16u);
    CP_ASYNC16(sB + O_UH, uph, 16u);
    CP_ASYNC16(sB + O_UL, upl, 16u);
    CP_COMMIT();

    for (int ch = 0; ch < nch; ch++) {
        if (ch + 1 < nch) {
            const uint32_t st = ((ch + 1) & 1) * F_STAGE;
            const int ko = (ch + 1) * BK;
            #pragma unroll
            for (int it = 0; it < 2; it++) {
                CP_ASYNC16(sA[it] + st,        aptr_hi[it] + ko, asz[it]);
                CP_ASYNC16(sA[it] + st + O_AL, aptr_lo[it] + ko, asz[it]);
            }
            CP_ASYNC16(sB + st + O_GH, gph + ko, 16u);
            CP_ASYNC16(sB + st + O_GL, gpl + ko, 16u);
            CP_ASYNC16(sB + st + O_UH, uph + ko, 16u);
            CP_ASYNC16(sB + st + O_UL, upl + ko, 16u);
            CP_COMMIT();
            CP_WAIT(1);
        } else {
            CP_WAIT(0);
        }
        __syncthreads();

        const uint32_t st = (ch & 1) * F_STAGE;
        #pragma unroll
        for (int ks = 0; ks < 2; ks++) {
            const int col = ks * 16 + ((lane >> 4) << 3);
            uint32_t ah[2][4], al[2][4];
            #pragma unroll
            for (int mf = 0; mf < 2; mf++) {
                const int row = wm * 32 + mf * 16 + (lane & 15);
                const uint32_t a = sbase + st + (row * STRIDE + col) * 2;
                LDSM4(ah[mf][0], ah[mf][1], ah[mf][2], ah[mf][3], a);
                LDSM4(al[mf][0], al[mf][1], al[mf][2], al[mf][3], a + O_AL);
            }
            uint32_t bh[4][2], bl[4][2];
            // ---- G part ----
            #pragma unroll
            for (int nf2 = 0; nf2 < 2; nf2++) {
                const int row = wn * 32 + nf2 * 16 + (lane & 15);
                const uint32_t a = sbase + st + (row * STRIDE + col) * 2;
                LDSM4(bh[nf2*2][0], bh[nf2*2+1][0], bh[nf2*2][1], bh[nf2*2+1][1], a + O_GH);
                LDSM4(bl[nf2*2][0], bl[nf2*2+1][0], bl[nf2*2][1], bl[nf2*2+1][1], a + O_GL);
            }
            #pragma unroll
            for (int mf = 0; mf < 2; mf++)
                #pragma unroll
                for (int nf = 0; nf < 4; nf++) {
                    MMA16816(accg[mf][nf], ah[mf][0], ah[mf][1], ah[mf][2], ah[mf][3],
                             bh[nf][0], bh[nf][1]);
                    MMA16816(accg[mf][nf], ah[mf][0], ah[mf][1], ah[mf][2], ah[mf][3],
                             bl[nf][0], bl[nf][1]);
                    MMA16816(accg[mf][nf], al[mf][0], al[mf][1], al[mf][2], al[mf][3],
                             bh[nf][0], bh[nf][1]);
                }
            // ---- U part (reuse B frag registers) ----
            #pragma unroll
            for (int nf2 = 0; nf2 < 2; nf2++) {
                const int row = wn * 32 + nf2 * 16 + (lane & 15);
                const uint32_t a = sbase + st + (row * STRIDE + col) * 2;
                LDSM4(bh[nf2*2][0], bh[nf2*2+1][0], bh[nf2*2][1], bh[nf2*2+1][1], a + O_UH);
                LDSM4(bl[nf2*2][0], bl[nf2*2+1][0], bl[nf2*2][1], bl[nf2*2+1][1], a + O_UL);
            }
            #pragma unroll
            for (int mf = 0; mf < 2; mf++)
                #pragma unroll
                for (int nf = 0; nf < 4; nf++) {
                    MMA16816(accu[mf][nf], ah[mf][0], ah[mf][1], ah[mf][2], ah[mf][3],
                             bh[nf][0], bh[nf][1]);
                    MMA16816(accu[mf][nf], ah[mf][0], ah[mf][1], ah[mf][2], ah[mf][3],
                             bl[nf][0], bl[nf][1]);
                    MMA16816(accu[mf][nf], al[mf][0], al[mf][1], al[mf][2], al[mf][3],
                             bh[nf][0], bh[nf][1]);
                }
        }
        __syncthreads();
    }

    // epilogue: silu(g)*u, split to bf16 hi/lo, packed bf16x2 stores
    const int quad = lane >> 2, tq = lane & 3;
    #pragma unroll
    for (int mf = 0; mf < 2; mf++) {
        #pragma unroll
        for (int half = 0; half < 2; half++) {
            const int m = wm * 32 + mf * 16 + half * 8 + quad;
            const int gm = m0 + m;
            if (gm >= cnt) continue;
            const size_t rowbase =
                (ROUTED ? (size_t)e * TKN + gm : (size_t)gm) * Ntot + n0 + wn * 32;
            #pragma unroll
            for (int nf = 0; nf < 4; nf++) {
                bf16 h2[2], l2[2];
                #pragma unroll
                for (int c = 0; c < 2; c++) {
                    const float g = accg[mf][nf][half * 2 + c];
                    const float u = accu[mf][nf][half * 2 + c];
                    const float h = g / (1.f + __expf(-g)) * u;
                    h2[c] = __float2bfloat16(h);
                    l2[c] = __float2bfloat16(h - __bfloat162float(h2[c]));
                }
                const size_t o = rowbase + nf * 8 + tq * 2;
                *(uint32_t*)(Mhi + o) = ((uint32_t)*(uint16_t*)&h2[1] << 16) | *(uint16_t*)&h2[0];
                *(uint32_t*)(Mlo + o) = ((uint32_t)*(uint16_t*)&l2[1] << 16) | *(uint16_t*)&l2[0];
            }
        }
    }
}

// ---------------- down GEMM (audited; EPI 1 = routed atomic, 2 = plain) ----------------
#define DBM 128
#define DBN 128
#define D_STAGE_ELEMS (4 * 128 * STRIDE)
#define GEMM_SMEM (2 * D_STAGE_ELEMS * 2)  // 81920

template<bool ROUTED, int EPI>
__global__ __launch_bounds__(256, 2) void down_hmma(
    const bf16* __restrict__ Ahi, const bf16* __restrict__ Alo,
    const bf16* __restrict__ Bhi, const bf16* __restrict__ Blo,
    float* __restrict__ C, int Ntot, int Ktot)
{
    extern __shared__ bf16 smem[];
    const int e   = ROUTED ? blockIdx.z : 0;
    const int cnt = ROUTED ? g_cnt[e] : TKN;
    const int m0  = blockIdx.y * DBM;
    if (m0 >= cnt) return;
    const int n0  = blockIdx.x * DBN;
    const int tid = threadIdx.x;
    const int wid = tid >> 5, lane = tid & 31;
    const int wm = wid >> 2, wn = wid & 3;

    const uint32_t sbase = smem_u32(smem);
    const int lr = tid >> 2;
    const int lc = (tid & 3) * 8;

    const bf16* aptr_hi[2]; const bf16* aptr_lo[2]; uint32_t asz[2];
    #pragma unroll
    for (int it = 0; it < 2; it++) {
        const int m = m0 + lr + it * 64;
        long row = 0;
        if (m < cnt) { row = ROUTED ? (long)e * TKN + m : m; asz[it] = 16; }
        else asz[it] = 0;
        aptr_hi[it] = Ahi + (size_t)row * Ktot + lc;
        aptr_lo[it] = Alo + (size_t)row * Ktot + lc;
    }
    const size_t wb = ROUTED ? (size_t)e * Ntot * Ktot : 0;
    const bf16* bptr_hi[2]; const bf16* bptr_lo[2];
    #pragma unroll
    for (int it = 0; it < 2; it++) {
        const int n = n0 + lr + it * 64;
        bptr_hi[it] = Bhi + wb + (size_t)n * Ktot + lc;
        bptr_lo[it] = Blo + wb + (size_t)n * Ktot + lc;
    }
    uint32_t sA[2];
    #pragma unroll
    for (int it = 0; it < 2; it++)
        sA[it] = sbase + ((lr + it * 64) * STRIDE + lc) * 2;
    const uint32_t O_AL = 128 * STRIDE * 2;
    const uint32_t O_BH = 2 * O_AL;
    const uint32_t O_BL = 3 * O_AL;
    const uint32_t STG = D_STAGE_ELEMS * 2;

    float acc[4][4][4];
    #pragma unroll
    for (int a = 0; a < 4; a++)
        #pragma unroll
        for (int b = 0; b < 4; b++)
            #pragma unroll
            for (int c = 0; c < 4; c++) acc[a][b][c] = 0.f;

    const int nch = Ktot / BK;

    #pragma unroll
    for (int it = 0; it < 2; it++) {
        CP_ASYNC16(sA[it],        aptr_hi[it], asz[it]);
        CP_ASYNC16(sA[it] + O_AL, aptr_lo[it], asz[it]);
        CP_ASYNC16(sA[it] + O_BH, bptr_hi[it], 16u);
        CP_ASYNC16(sA[it] + O_BL, bptr_lo[it], 16u);
    }
    CP_COMMIT();

    for (int ch = 0; ch < nch; ch++) {
        if (ch + 1 < nch) {
            const uint32_t st = ((ch + 1) & 1) * STG;
            const int ko = (ch + 1) * BK;
            #pragma unroll
            for (int it = 0; it < 2; it++) {
                CP_ASYNC16(sA[it] + st,        aptr_hi[it] + ko, asz[it]);
                CP_ASYNC16(sA[it] + st + O_AL, aptr_lo[it] + ko, asz[it]);
                CP_ASYNC16(sA[it] + st + O_BH, bptr_hi[it] + ko, 16u);
                CP_ASYNC16(sA[it] + st + O_BL, bptr_lo[it] + ko, 16u);
            }
            CP_COMMIT();
            CP_WAIT(1);
        } else {
            CP_WAIT(0);
        }
        __syncthreads();

        const uint32_t st = (ch & 1) * STG;
        #pragma unroll
        for (int ks = 0; ks < 2; ks++) {
            const int col = ks * 16 + ((lane >> 4) << 3);
            uint32_t ah[4][4], al[4][4];
            #pragma unroll
            for (int mf = 0; mf < 4; mf++) {
                const int row = wm * 64 + mf * 16 + (lane & 15);
                const uint32_t a = sbase + st + (row * STRIDE + col) * 2;
                LDSM4(ah[mf][0], ah[mf][1], ah[mf][2], ah[mf][3], a);
                LDSM4(al[mf][0], al[mf][1], al[mf][2], al[mf][3], a + O_AL);
            }
            uint32_t bh[4][2], bl[4][2];
            #pragma unroll
            for (int nf2 = 0; nf2 < 2; nf2++) {
                const int row = wn * 32 + nf2 * 16 + (lane & 15);
                const uint32_t a = sbase + st + (row * STRIDE + col) * 2;
                LDSM4(bh[nf2*2][0], bh[nf2*2+1][0], bh[nf2*2][1], bh[nf2*2+1][1], a + O_BH);
                LDSM4(bl[nf2*2][0], bl[nf2*2+1][0], bl[nf2*2][1], bl[nf2*2+1][1], a + O_BL);
            }
            #pragma unroll
            for (int mf = 0; mf < 4; mf++)
                #pragma unroll
                for (int nf = 0; nf < 4; nf++) {
                    MMA16816(acc[mf][nf], ah[mf][0], ah[mf][1], ah[mf][2], ah[mf][3],
                             bh[nf][0], bh[nf][1]);
                    MMA16816(acc[mf][nf], ah[mf][0], ah[mf][1], ah[mf][2], ah[mf][3],
                             bl[nf][0], bl[nf][1]);
                    MMA16816(acc[mf][nf], al[mf][0], al[mf][1], al[mf][2], al[mf][3],
                             bh[nf][0], bh[nf][1]);
                }
        }
        __syncthreads();
    }

    const int quad = lane >> 2, tq = lane & 3;
    #pragma unroll
    for (int mf = 0; mf < 4; mf++) {
        #pragma unroll
        for (int half = 0; half < 2; half++) {
            const int m = wm * 64 + mf * 16 + half * 8 + quad;
            const int gm = m0 + m;
            if (gm >= cnt) continue;
            if (EPI == 1) {
                const int   t = g_tok[e][gm];
                const float w = g_wt[e][gm];
                float* o = C + (size_t)t * HD + n0 + wn * 32 + tq * 2;
                #pragma unroll
                for (int nf = 0; nf < 4; nf++) {
                    atomicAdd(&o[nf * 8 + 0], w * acc[mf][nf][half * 2 + 0]);
                    atomicAdd(&o[nf * 8 + 1], w * acc[mf][nf][half * 2 + 1]);
                }
            } else {
                float* o = C + (size_t)gm * HD + n0 + wn * 32 + tq * 2;
                #pragma unroll
                for (int nf = 0; nf < 4; nf++) {
                    o[nf * 8 + 0] = acc[mf][nf][half * 2 + 0];
                    o[nf * 8 + 1] = acc[mf][nf][half * 2 + 1];
                }
            }
        }
    }
}

// ---------------- launch ----------------
#define GETSYM(var, sym) void* var = nullptr; cudaGetSymbolAddress(&var, sym)

extern "C" void kernel_launch(void* const* d_in, const int* in_sizes, int n_in,
                              void* d_out, int out_size) {
    const float* x  = (const float*)d_in[0];
    const float* gw = (const float*)d_in[1];
    const float* gp = (const float*)d_in[2];
    const float* up = (const float*)d_in[3];
    const float* dp = (const float*)d_in[4];
    const float* sg = (const float*)d_in[5];
    const float* su = (const float*)d_in[6];
    const float* sd = (const float*)d_in[7];
    float* out = (float*)d_out;

    GETSYM(p_xhi, g_xhi);   GETSYM(p_xlo, g_xlo);
    GETSYM(p_gphi, g_gphi); GETSYM(p_gplo, g_gplo);
    GETSYM(p_uphi, g_uphi); GETSYM(p_uplo, g_uplo);
    GETSYM(p_dphi, g_dphi); GETSYM(p_dplo, g_dplo);
    GETSYM(p_sghi, g_sghi); GETSYM(p_sglo, g_sglo);
    GETSYM(p_suhi, g_suhi); GETSYM(p_sulo, g_sulo);
    GETSYM(p_sdhi, g_sdhi); GETSYM(p_sdlo, g_sdlo);
    GETSYM(p_midhi, g_midhi); GETSYM(p_midlo, g_midlo);
    GETSYM(p_smidhi, g_smidhi); GETSYM(p_smidlo, g_smidlo);

    cudaFuncSetAttribute(gateup_fused<true>,  cudaFuncAttributeMaxDynamicSharedMemorySize, FUSE_SMEM);
    cudaFuncSetAttribute(gateup_fused<false>, cudaFuncAttributeMaxDynamicSharedMemorySize, FUSE_SMEM);
    cudaFuncSetAttribute(down_hmma<true, 1>,  cudaFuncAttributeMaxDynamicSharedMemorySize, GEMM_SMEM);
    cudaFuncSetAttribute(down_hmma<false, 2>, cudaFuncAttributeMaxDynamicSharedMemorySize, GEMM_SMEM);

    zero_cnt_kernel<<<1, 32>>>();                                       // 1
    routing_kernel<<<TKN / 8, 256>>>(x, gw);                            // 2
    split_kernel<<<(TKN * HD / 4 + 255) / 256, 256>>>(                  // 3
        x, (bf16*)p_xhi, (bf16*)p_xlo, TKN * HD / 4);
    conv_all_kernel<<<3 * NB_GP + 3 * NB_SG, dim3(32, 8)>>>(            // 4
        gp, up, dp, sg, su, sd);

    gateup_fused<true><<<dim3(FDI / 64, TKN / 128, NE), 256, FUSE_SMEM>>>(   // 5
        (const bf16*)p_xhi, (const bf16*)p_xlo,
        (const bf16*)p_gphi, (const bf16*)p_gplo,
        (const bf16*)p_uphi, (const bf16*)p_uplo,
        (bf16*)p_midhi, (bf16*)p_midlo, FDI, HD);
    gateup_fused<false><<<dim3(SFD / 64, TKN / 128), 256, FUSE_SMEM>>>(      // 6 (ncu)
        (const bf16*)p_xhi, (const bf16*)p_xlo,
        (const bf16*)p_sghi, (const bf16*)p_sglo,
        (const bf16*)p_suhi, (const bf16*)p_sulo,
        (bf16*)p_smidhi, (bf16*)p_smidlo, SFD, HD);

    down_hmma<false, 2><<<dim3(HD / DBN, TKN / DBM), 256, GEMM_SMEM>>>(      // 7
        (const bf16*)p_smidhi, (const bf16*)p_smidlo,
        (const bf16*)p_sdhi, (const bf16*)p_sdlo, out, HD, SFD);
    down_hmma<true, 1><<<dim3(HD / DBN, TKN / DBM, NE), 256, GEMM_SMEM>>>(   // 8
        (const bf16*)p_midhi, (const bf16*)p_midlo,
        (const bf16*)p_dphi, (const bf16*)p_dplo, out, HD, FDI);
}